// round 13
// baseline (speedup 1.0000x reference)
#include <cuda_runtime.h>
#include <math.h>

typedef unsigned long long u64;

// ---------------- packed f32x2 helpers (sm_103a) ----------------
__device__ __forceinline__ u64 pack2(float a, float b){ u64 r; asm("mov.b64 %0,{%1,%2};":"=l"(r):"f"(a),"f"(b)); return r; }
__device__ __forceinline__ u64 pack1(float a){ u64 r; asm("mov.b64 %0,{%1,%1};":"=l"(r):"f"(a)); return r; }
__device__ __forceinline__ void unpack2(u64 v, float& a, float& b){ asm("mov.b64 {%0,%1},%2;":"=f"(a),"=f"(b):"l"(v)); }
__device__ __forceinline__ u64 fma2(u64 a,u64 b,u64 c){ u64 d; asm("fma.rn.f32x2 %0,%1,%2,%3;":"=l"(d):"l"(a),"l"(b),"l"(c)); return d; }
__device__ __forceinline__ float hadd2(u64 v){ float a,b; unpack2(v,a,b); return a+b; }

// HW tanh (MUFU.TANH): verified rel_err ~1.9e-6 end-to-end (R11)
__device__ __forceinline__ float tanh_hw(float x){
    float y; asm("tanh.approx.f32 %0, %1;" : "=f"(y) : "f"(x)); return y;
}
__device__ __forceinline__ float sig_hw(float x){
    return fmaf(0.5f, tanh_hw(0.5f * x), 0.5f);
}
__device__ __forceinline__ float gelu1(float v){
    float u = (v * 0.7978845608028654f) * fmaf(0.044715f * v, v, 1.0f);
    float hv = 0.5f * v;
    return fmaf(hv, tanh_hw(u), hv);
}

// ---------------- folded-weight scratch ----------------
__device__ float g_A[1024];   // (wq^T wk) / sqrt(32)
__device__ float g_W1[1024];  // w_ih @ Wo @ wv
__device__ float g_r[32];     // (wk^T bq) / sqrt(32)
__device__ float g_c1[32];    // w_ih @ (Wo bv + bo) + b_ih + b_hh

// ---------------- prep kernel ----------------
__global__ void prep_kernel(const float* __restrict__ ipw, const float* __restrict__ ipb,
                            const float* __restrict__ opw, const float* __restrict__ opb,
                            const float* __restrict__ wih, const float* __restrict__ bih,
                            const float* __restrict__ bhh)
{
    __shared__ float T[1024];
    __shared__ float t2[32];
    const float inv = 0.17677669529663688f;
    int tid = threadIdx.x;
    int i = tid >> 5, j = tid & 31;
    const float* wq = ipw;
    const float* wk = ipw + 1024;
    const float* wv = ipw + 2048;

    float a = 0.f, t = 0.f;
    #pragma unroll 8
    for (int m = 0; m < 32; m++){
        a += wq[m*32 + i] * wk[m*32 + j];
        t += opw[i*32 + m] * wv[m*32 + j];
    }
    g_A[i*32 + j] = a * inv;
    T[i*32 + j] = t;

    if (i == 0){
        float rr = 0.f, tt = 0.f;
        #pragma unroll 8
        for (int m = 0; m < 32; m++){
            rr += ipb[m] * wk[m*32 + j];
            tt += opw[j*32 + m] * ipb[64 + m];
        }
        g_r[j] = rr * inv;
        t2[j] = tt + opb[j];
    }
    __syncthreads();

    float w1 = 0.f;
    #pragma unroll 8
    for (int m = 0; m < 32; m++)
        w1 += wih[i*32 + m] * T[m*32 + j];
    g_W1[i*32 + j] = w1;

    if (i == 0){
        float c = 0.f;
        #pragma unroll 8
        for (int m = 0; m < 32; m++)
            c += wih[j*32 + m] * t2[m];
        g_c1[j] = c + bih[j] + bhh[j];
    }
}

// ---------------- fused main: one row/thread; outer-product matvecs (transposed weights) ----------------
__global__ __launch_bounds__(256) void fused_kernel(
    const float* __restrict__ x,
    const float* __restrict__ embw, const float* __restrict__ embb,
    const float* __restrict__ whh,
    const float* __restrict__ decw, const float* __restrict__ decb,
    const float* __restrict__ outw, const float* __restrict__ outb,
    float* __restrict__ out, int B)
{
    // transposed layouts: sXT[c*32 + l] = X[l][c]  (column c contiguous)
    __shared__ __align__(16) float sAT [1024];
    __shared__ __align__(16) float sW1T[1024];
    __shared__ __align__(16) float sWhT[1024];
    __shared__ __align__(16) float sDec[160];    // row-major (5 outputs)
    __shared__ __align__(16) float sR[32];
    __shared__ __align__(16) float sEmbT[160];   // [k][l]
    __shared__ __align__(16) float sC1[32];
    __shared__ __align__(16) float sEmbB[32];
    __shared__ float sDecB[8];
    __shared__ float sOw[16];
    __shared__ float sOb[4];

    const int tid = threadIdx.x;
    for (int i = tid; i < 1024; i += 256){
        int l = i >> 5, c = i & 31;
        int t = c*32 + l;
        sAT [t] = g_A[i];
        sW1T[t] = g_W1[i];
        sWhT[t] = whh[i];
    }
    if (tid < 160){
        sDec[tid] = decw[tid];
        int l = tid / 5, k = tid % 5;
        sEmbT[k*32 + l] = embw[tid];
    }
    if (tid < 32){ sC1[tid] = g_c1[tid]; sR[tid] = g_r[tid]; sEmbB[tid] = embb[tid]; }
    if (tid < 15) sOw[tid] = outw[tid];
    if (tid < 5)  sDecB[tid] = decb[tid];
    if (tid < 3)  sOb[tid] = outb[tid];
    __syncthreads();

    int r = blockIdx.x * 256 + tid;
    if (r >= B) return;

    // ---- load x row (10 floats, 8B aligned) ----
    float xv[10];
    {
        const float2* xp = reinterpret_cast<const float2*>(x + (long long)r*10);
        #pragma unroll
        for (int k = 0; k < 5; k++){ float2 t = xp[k]; xv[2*k] = t.x; xv[2*k+1] = t.y; }
    }
    u64 xp0[5], xp1[5];
    #pragma unroll
    for (int k = 0; k < 5; k++){ xp0[k] = pack1(xv[k]); xp1[k] = pack1(xv[5+k]); }

    // ---- embedding (already outer-product over 5 input dims) ----
    u64 e0p[16], dep[16];
    const u64* ebp = reinterpret_cast<const u64*>(sEmbB);
    #pragma unroll
    for (int i = 0; i < 16; i++){
        u64 a0 = ebp[i], a1 = a0;
        #pragma unroll
        for (int k = 0; k < 5; k++){
            u64 w = *reinterpret_cast<const u64*>(sEmbT + k*32 + 2*i);
            a0 = fma2(w, xp0[k], a0);
            a1 = fma2(w, xp1[k], a1);
        }
        float v00, v10, v01, v11;
        unpack2(a0, v00, v10);
        unpack2(a1, v01, v11);
        float g00 = gelu1(v00), g10 = gelu1(v10);
        float g01 = gelu1(v01), g11 = gelu1(v11);
        e0p[i] = pack2(g00, g10);
        dep[i] = pack2(g01 - g00, g11 - g10);
    }

    // ---- attention: w = A de via outer product; then packed dots ----
    u64 w[16];
    #pragma unroll
    for (int i = 0; i < 16; i++) w[i] = 0ull;
    #pragma unroll
    for (int i = 0; i < 16; i++){
        float lo, hi;
        unpack2(dep[i], lo, hi);
        u64 b0 = pack1(lo), b1 = pack1(hi);
        const ulonglong2* col0 = reinterpret_cast<const ulonglong2*>(sAT + (2*i)*32);
        const ulonglong2* col1 = reinterpret_cast<const ulonglong2*>(sAT + (2*i+1)*32);
        #pragma unroll
        for (int k = 0; k < 8; k++){
            ulonglong2 v0 = col0[k], v1 = col1[k];
            w[2*k]   = fma2(v0.x, b0, w[2*k]);
            w[2*k+1] = fma2(v0.y, b0, w[2*k+1]);
            w[2*k]   = fma2(v1.x, b1, w[2*k]);
            w[2*k+1] = fma2(v1.y, b1, w[2*k+1]);
        }
    }
    u64 accE = 0ull, accD = 0ull, accR = 0ull;
    const u64* rp = reinterpret_cast<const u64*>(sR);
    #pragma unroll
    for (int i = 0; i < 16; i++){
        accE = fma2(e0p[i], w[i], accE);
        accD = fma2(dep[i], w[i], accD);
        accR = fma2(rp[i], dep[i], accR);
    }
    float d0 = hadd2(accE) + hadd2(accR);
    float d1 = d0 + hadd2(accD);
    float a01 = sig_hw(d0);
    float a11 = sig_hw(d1);

    // ---- m0 = e0 + a01*de (in place) ----
    {
        u64 a01p = pack1(a01);
        #pragma unroll
        for (int i = 0; i < 16; i++) e0p[i] = fma2(a01p, dep[i], e0p[i]);
    }

    // ---- h1 = tanh(W1 m0 + c1): outer product, y init = c1 pairs ----
    u64 h1p[16];
    {
        u64 y[16];
        const u64* c1p = reinterpret_cast<const u64*>(sC1);
        #pragma unroll
        for (int i = 0; i < 16; i++) y[i] = c1p[i];
        #pragma unroll
        for (int i = 0; i < 16; i++){
            float lo, hi;
            unpack2(e0p[i], lo, hi);
            u64 b0 = pack1(lo), b1 = pack1(hi);
            const ulonglong2* col0 = reinterpret_cast<const ulonglong2*>(sW1T + (2*i)*32);
            const ulonglong2* col1 = reinterpret_cast<const ulonglong2*>(sW1T + (2*i+1)*32);
            #pragma unroll
            for (int k = 0; k < 8; k++){
                ulonglong2 v0 = col0[k], v1 = col1[k];
                y[2*k]   = fma2(v0.x, b0, y[2*k]);
                y[2*k+1] = fma2(v0.y, b0, y[2*k+1]);
                y[2*k]   = fma2(v1.x, b1, y[2*k]);
                y[2*k+1] = fma2(v1.y, b1, y[2*k+1]);
            }
        }
        #pragma unroll
        for (int i = 0; i < 16; i++){
            float v0, v1;
            unpack2(y[i], v0, v1);
            h1p[i] = pack2(tanh_hw(v0), tanh_hw(v1));
        }
    }

    // ---- m1 = m0 + (a11-a01)*de (in place; dep dies) ----
    {
        u64 adp = pack1(a11 - a01);
        #pragma unroll
        for (int i = 0; i < 16; i++) e0p[i] = fma2(adp, dep[i], e0p[i]);
    }

    // ---- h2 = tanh(W1 m1 + Wh h1 + c1): fused outer product over both matrices ----
    {
        u64 y[16];
        const u64* c1p = reinterpret_cast<const u64*>(sC1);
        #pragma unroll
        for (int i = 0; i < 16; i++) y[i] = c1p[i];
        #pragma unroll
        for (int i = 0; i < 16; i++){
            float alo, ahi, blo, bhi;
            unpack2(e0p[i], alo, ahi);
            unpack2(h1p[i], blo, bhi);
            u64 a0 = pack1(alo), a1 = pack1(ahi);
            u64 b0 = pack1(blo), b1 = pack1(bhi);
            const ulonglong2* cw0 = reinterpret_cast<const ulonglong2*>(sW1T + (2*i)*32);
            const ulonglong2* cw1 = reinterpret_cast<const ulonglong2*>(sW1T + (2*i+1)*32);
            const ulonglong2* ch0 = reinterpret_cast<const ulonglong2*>(sWhT + (2*i)*32);
            const ulonglong2* ch1 = reinterpret_cast<const ulonglong2*>(sWhT + (2*i+1)*32);
            #pragma unroll
            for (int k = 0; k < 8; k++){
                ulonglong2 vw0 = cw0[k], vw1 = cw1[k];
                ulonglong2 vh0 = ch0[k], vh1 = ch1[k];
                y[2*k]   = fma2(vw0.x, a0, y[2*k]);
                y[2*k+1] = fma2(vw0.y, a0, y[2*k+1]);
                y[2*k]   = fma2(vw1.x, a1, y[2*k]);
                y[2*k+1] = fma2(vw1.y, a1, y[2*k+1]);
                y[2*k]   = fma2(vh0.x, b0, y[2*k]);
                y[2*k+1] = fma2(vh0.y, b0, y[2*k+1]);
                y[2*k]   = fma2(vh1.x, b1, y[2*k]);
                y[2*k+1] = fma2(vh1.y, b1, y[2*k+1]);
            }
        }
        // h2 -> dep (register reuse)
        #pragma unroll
        for (int i = 0; i < 16; i++){
            float v0, v1;
            unpack2(y[i], v0, v1);
            dep[i] = pack2(tanh_hw(v0), tanh_hw(v1));
        }
    }

    // ---- decode (row form; tiny): d = gelu(Dec h2 + b) ; out = Ow d + ob ----
    float dv[5];
    #pragma unroll
    for (int j = 0; j < 5; j++){
        const ulonglong2* rd = reinterpret_cast<const ulonglong2*>(sDec + j*32);
        u64 acc = 0ull;
        #pragma unroll
        for (int c = 0; c < 8; c++){
            ulonglong2 v = rd[c];
            acc = fma2(v.x, dep[2*c],   acc);
            acc = fma2(v.y, dep[2*c+1], acc);
        }
        dv[j] = gelu1(hadd2(acc) + sDecB[j]);
    }
    #pragma unroll
    for (int o = 0; o < 3; o++){
        float acc = sOb[o];
        #pragma unroll
        for (int j = 0; j < 5; j++) acc = fmaf(sOw[o*5 + j], dv[j], acc);
        out[(long long)r*3 + o] = acc;
    }
}

// ---------------- launch ----------------
extern "C" void kernel_launch(void* const* d_in, const int* in_sizes, int n_in,
                              void* d_out, int out_size)
{
    const float* x      = (const float*)d_in[0];
    const float* embw   = (const float*)d_in[1];
    const float* embb   = (const float*)d_in[2];
    const float* ipw    = (const float*)d_in[3];
    const float* ipb    = (const float*)d_in[4];
    const float* opw    = (const float*)d_in[5];
    const float* opb    = (const float*)d_in[6];
    const float* wih    = (const float*)d_in[7];
    const float* bih    = (const float*)d_in[8];
    const float* whh    = (const float*)d_in[9];
    const float* bhh    = (const float*)d_in[10];
    const float* decw   = (const float*)d_in[11];
    const float* decb   = (const float*)d_in[12];
    const float* outw   = (const float*)d_in[13];
    const float* outb   = (const float*)d_in[14];
    float* out = (float*)d_out;

    int B = in_sizes[0] / 10;

    prep_kernel<<<1, 1024>>>(ipw, ipb, opw, opb, wih, bih, bhh);

    int blocks = (B + 255) / 256;
    fused_kernel<<<blocks, 256>>>(x, embw, embb, whh, decw, decb, outw, outb, out, B);
}